// round 3
// baseline (speedup 1.0000x reference)
#include <cuda_runtime.h>
#include <cstdint>

#define N_NODESC 100000
#define N_EDGESC 2500000
#define IN_CH 32
#define HID 16
#define OUT_CH 64
#define NUM_GRAPHS 64

// ---------------- scratch (static device globals; 16B-aligned for v4 access) ----------------
__device__ __align__(16) float g_y[N_NODESC * HID];     // x @ w1_l^T (pre-transformed)
__device__ __align__(16) float g_xr[N_NODESC * HID];    // x @ w1_r^T
__device__ __align__(16) float g_h1[N_NODESC * HID];    // layer-1 output
__device__ __align__(16) float g_agg1[N_NODESC * HID];  // scatter accumulator layer 1
__device__ __align__(16) float g_agg2[N_NODESC * HID];  // scatter accumulator layer 2
__device__ __align__(16) float g_cnt[N_NODESC];         // per-node in-degree
__device__ __align__(16) float g_gacc[NUM_GRAPHS * OUT_CH];
__device__ __align__(16) float g_gcnt[NUM_GRAPHS];

__device__ __forceinline__ void red_add_v4(float* p, float a, float b, float c, float d) {
    asm volatile("red.global.add.v4.f32 [%0], {%1, %2, %3, %4};"
                 :: "l"(p), "f"(a), "f"(b), "f"(c), "f"(d) : "memory");
}

// ---------------- Kernel A: pre-transform x -> y, xr; zero accumulators ----------------
__global__ void __launch_bounds__(256) kPre(const float* __restrict__ x,
                                            const float* __restrict__ w1l,
                                            const float* __restrict__ w1r) {
    __shared__ __align__(16) float swl[HID * IN_CH];
    __shared__ __align__(16) float swr[HID * IN_CH];
    int t = threadIdx.x;
    for (int i = t; i < HID * IN_CH; i += blockDim.x) {
        swl[i] = w1l[i];
        swr[i] = w1r[i];
    }
    __syncthreads();

    int n = blockIdx.x * blockDim.x + t;
    if (n >= N_NODESC) return;

    if (n < NUM_GRAPHS * OUT_CH) g_gacc[n] = 0.0f;
    if (n < NUM_GRAPHS) g_gcnt[n] = 0.0f;

    float xv[IN_CH];
    const float4* xp = reinterpret_cast<const float4*>(x + (size_t)n * IN_CH);
#pragma unroll
    for (int i = 0; i < IN_CH / 4; i++) {
        float4 v = __ldg(xp + i);
        xv[4 * i + 0] = v.x; xv[4 * i + 1] = v.y; xv[4 * i + 2] = v.z; xv[4 * i + 3] = v.w;
    }

    float yl[HID], yr[HID];
#pragma unroll
    for (int o = 0; o < HID; o++) {
        float al = 0.0f, ar = 0.0f;
#pragma unroll
        for (int kk = 0; kk < IN_CH / 4; kk++) {
            float4 wl = *reinterpret_cast<float4*>(&swl[o * IN_CH + kk * 4]);
            float4 wr = *reinterpret_cast<float4*>(&swr[o * IN_CH + kk * 4]);
            al += xv[kk*4+0]*wl.x + xv[kk*4+1]*wl.y + xv[kk*4+2]*wl.z + xv[kk*4+3]*wl.w;
            ar += xv[kk*4+0]*wr.x + xv[kk*4+1]*wr.y + xv[kk*4+2]*wr.z + xv[kk*4+3]*wr.w;
        }
        yl[o] = al; yr[o] = ar;
    }

    float4* yp  = reinterpret_cast<float4*>(g_y  + (size_t)n * HID);
    float4* rp  = reinterpret_cast<float4*>(g_xr + (size_t)n * HID);
    float4* a1p = reinterpret_cast<float4*>(g_agg1 + (size_t)n * HID);
#pragma unroll
    for (int i = 0; i < HID / 4; i++) {
        yp[i] = make_float4(yl[4*i], yl[4*i+1], yl[4*i+2], yl[4*i+3]);
        rp[i] = make_float4(yr[4*i], yr[4*i+1], yr[4*i+2], yr[4*i+3]);
        a1p[i] = make_float4(0.f, 0.f, 0.f, 0.f);
    }
    g_cnt[n] = 0.0f;
}

// ---------------- Kernel B/D: edge scatter (gather 16f from src, red into dst) ----------------
__global__ void __launch_bounds__(256) kScatter(const int* __restrict__ ei,
                                                const float* __restrict__ val,
                                                float* __restrict__ acc,
                                                int addCount) {
    int e = blockIdx.x * blockDim.x + threadIdx.x;
    if (e >= N_EDGESC) return;
    int s = __ldg(&ei[e]);
    int d = __ldg(&ei[N_EDGESC + e]);

    const float4* v = reinterpret_cast<const float4*>(val + (size_t)s * HID);
    float4 v0 = __ldg(v + 0);
    float4 v1 = __ldg(v + 1);
    float4 v2 = __ldg(v + 2);
    float4 v3 = __ldg(v + 3);

    float* a = acc + (size_t)d * HID;
    red_add_v4(a + 0,  v0.x, v0.y, v0.z, v0.w);
    red_add_v4(a + 4,  v1.x, v1.y, v1.z, v1.w);
    red_add_v4(a + 8,  v2.x, v2.y, v2.z, v2.w);
    red_add_v4(a + 12, v3.x, v3.y, v3.z, v3.w);
    if (addCount) atomicAdd(&g_cnt[d], 1.0f);
}

// ---------------- Kernel C: h1 = relu(agg1/cnt + b1 + xr); zero agg2 ----------------
__global__ void __launch_bounds__(256) kLayer1(const float* __restrict__ b1) {
    int idx = blockIdx.x * blockDim.x + threadIdx.x;
    if (idx >= N_NODESC * 4) return;
    int n = idx >> 2;
    int c = idx & 3;

    float inv = 1.0f / fmaxf(g_cnt[n], 1.0f);
    float4 a = *reinterpret_cast<float4*>(&g_agg1[(size_t)n * HID + c * 4]);
    float4 r = *reinterpret_cast<float4*>(&g_xr[(size_t)n * HID + c * 4]);
    float4 bb = __ldg(reinterpret_cast<const float4*>(b1) + c);

    float4 h;
    h.x = fmaxf(a.x * inv + bb.x + r.x, 0.0f);
    h.y = fmaxf(a.y * inv + bb.y + r.y, 0.0f);
    h.z = fmaxf(a.z * inv + bb.z + r.z, 0.0f);
    h.w = fmaxf(a.w * inv + bb.w + r.w, 0.0f);

    *reinterpret_cast<float4*>(&g_h1[(size_t)n * HID + c * 4]) = h;
    *reinterpret_cast<float4*>(&g_agg2[(size_t)n * HID + c * 4]) = make_float4(0.f, 0.f, 0.f, 0.f);
}

// ---------------- Kernel E: h2 = (agg2/cnt)@w2_l^T + b2 + h1@w2_r^T; graph accumulate ----------------
__global__ void __launch_bounds__(128) kLayer2(const int* __restrict__ batch,
                                               const float* __restrict__ w2l,
                                               const float* __restrict__ b2,
                                               const float* __restrict__ w2r) {
    __shared__ __align__(16) float swl[HID * OUT_CH];   // stored transposed [k][o]
    __shared__ __align__(16) float swr[HID * OUT_CH];
    __shared__ __align__(16) float sb2[OUT_CH];
    int t = threadIdx.x;
    for (int i = t; i < HID * OUT_CH; i += blockDim.x) {
        int o = i / HID, k = i % HID;   // input layout [o][k]
        swl[k * OUT_CH + o] = w2l[i];
        swr[k * OUT_CH + o] = w2r[i];
    }
    for (int i = t; i < OUT_CH; i += blockDim.x) sb2[i] = b2[i];
    __syncthreads();

    int n = blockIdx.x * blockDim.x + t;
    if (n >= N_NODESC) return;

    float inv = 1.0f / fmaxf(g_cnt[n], 1.0f);
    float av[HID], hv[HID];
    const float4* ap = reinterpret_cast<const float4*>(g_agg2 + (size_t)n * HID);
    const float4* hp = reinterpret_cast<const float4*>(g_h1 + (size_t)n * HID);
#pragma unroll
    for (int i = 0; i < HID / 4; i++) {
        float4 a = ap[i];
        av[4*i] = a.x * inv; av[4*i+1] = a.y * inv; av[4*i+2] = a.z * inv; av[4*i+3] = a.w * inv;
        float4 h = hp[i];
        hv[4*i] = h.x; hv[4*i+1] = h.y; hv[4*i+2] = h.z; hv[4*i+3] = h.w;
    }

    float acc[OUT_CH];
#pragma unroll
    for (int o = 0; o < OUT_CH; o++) acc[o] = sb2[o];

#pragma unroll
    for (int k = 0; k < HID; k++) {
        float ak = av[k], hk = hv[k];
#pragma unroll
        for (int o = 0; o < OUT_CH; o += 4) {
            float4 wl = *reinterpret_cast<float4*>(&swl[k * OUT_CH + o]);
            float4 wr = *reinterpret_cast<float4*>(&swr[k * OUT_CH + o]);
            acc[o + 0] += ak * wl.x + hk * wr.x;
            acc[o + 1] += ak * wl.y + hk * wr.y;
            acc[o + 2] += ak * wl.z + hk * wr.z;
            acc[o + 3] += ak * wl.w + hk * wr.w;
        }
    }

    int g = __ldg(&batch[n]);
    float* gp = g_gacc + (size_t)g * OUT_CH;
#pragma unroll
    for (int o = 0; o < OUT_CH; o += 4)
        red_add_v4(gp + o, acc[o], acc[o + 1], acc[o + 2], acc[o + 3]);
    atomicAdd(&g_gcnt[g], 1.0f);
}

// ---------------- Kernel F: final divide into d_out ----------------
__global__ void __launch_bounds__(256) kFinal(float* __restrict__ out) {
    int i = blockIdx.x * blockDim.x + threadIdx.x;
    if (i >= NUM_GRAPHS * OUT_CH) return;
    out[i] = g_gacc[i] / fmaxf(g_gcnt[i >> 6], 1.0f);
}

// ---------------- launch ----------------
extern "C" void kernel_launch(void* const* d_in, const int* in_sizes, int n_in,
                              void* d_out, int out_size) {
    const float* x    = (const float*)d_in[0];
    const int*   ei   = (const int*)d_in[1];      // int32 (JAX x64 disabled)
    const int*   batch= (const int*)d_in[2];      // int32
    const float* w1l  = (const float*)d_in[3];
    const float* b1   = (const float*)d_in[4];
    const float* w1r  = (const float*)d_in[5];
    const float* w2l  = (const float*)d_in[6];
    const float* b2   = (const float*)d_in[7];
    const float* w2r  = (const float*)d_in[8];
    float* out = (float*)d_out;

    float* gy;   cudaGetSymbolAddress((void**)&gy,   g_y);
    float* gh1;  cudaGetSymbolAddress((void**)&gh1,  g_h1);
    float* ga1;  cudaGetSymbolAddress((void**)&ga1,  g_agg1);
    float* ga2;  cudaGetSymbolAddress((void**)&ga2,  g_agg2);

    const int TB = 256;
    int nodeBlocks = (N_NODESC + TB - 1) / TB;
    int edgeBlocks = (N_EDGESC + TB - 1) / TB;
    int chBlocks   = (N_NODESC * 4 + TB - 1) / TB;

    kPre<<<nodeBlocks, TB>>>(x, w1l, w1r);
    kScatter<<<edgeBlocks, TB>>>(ei, gy, ga1, 1);
    kLayer1<<<chBlocks, TB>>>(b1);
    kScatter<<<edgeBlocks, TB>>>(ei, gh1, ga2, 0);
    kLayer2<<<(N_NODESC + 127) / 128, 128>>>(batch, w2l, b2, w2r);
    kFinal<<<(NUM_GRAPHS * OUT_CH + TB - 1) / TB, TB>>>(out);
}

// round 4
// speedup vs baseline: 2.1382x; 2.1382x over previous
#include <cuda_runtime.h>
#include <cstdint>

#define N_NODESC 100000
#define N_EDGESC 2500000
#define IN_CH 32
#define HID 16
#define OUT_CH 64
#define NUM_GRAPHS 64

// ---------------- scratch ----------------
__device__ __align__(16) float g_y[N_NODESC * HID];
__device__ __align__(16) float g_xr[N_NODESC * HID];
__device__ __align__(16) float g_h1[N_NODESC * HID];
__device__ __align__(16) float g_agg1[N_NODESC * HID];
__device__ __align__(16) float g_agg2[N_NODESC * HID];
__device__ __align__(16) float g_cnt[N_NODESC];
__device__ __align__(16) float g_gacc[NUM_GRAPHS * OUT_CH];
__device__ __align__(16) float g_gcnt[NUM_GRAPHS];

__device__ __forceinline__ void red_add_v4(float* p, float a, float b, float c, float d) {
    asm volatile("red.global.add.v4.f32 [%0], {%1, %2, %3, %4};"
                 :: "l"(p), "f"(a), "f"(b), "f"(c), "f"(d) : "memory");
}

// ---------------- Kernel A: pre-transform x -> y, xr; zero accumulators ----------------
__global__ void __launch_bounds__(256) kPre(const float* __restrict__ x,
                                            const float* __restrict__ w1l,
                                            const float* __restrict__ w1r) {
    __shared__ __align__(16) float swl[HID * IN_CH];
    __shared__ __align__(16) float swr[HID * IN_CH];
    int t = threadIdx.x;
    for (int i = t; i < HID * IN_CH; i += blockDim.x) {
        swl[i] = w1l[i];
        swr[i] = w1r[i];
    }
    __syncthreads();

    int n = blockIdx.x * blockDim.x + t;
    if (n >= N_NODESC) return;

    if (n < NUM_GRAPHS * OUT_CH) g_gacc[n] = 0.0f;
    if (n < NUM_GRAPHS) g_gcnt[n] = 0.0f;

    float xv[IN_CH];
    const float4* xp = reinterpret_cast<const float4*>(x + (size_t)n * IN_CH);
#pragma unroll
    for (int i = 0; i < IN_CH / 4; i++) {
        float4 v = __ldg(xp + i);
        xv[4 * i + 0] = v.x; xv[4 * i + 1] = v.y; xv[4 * i + 2] = v.z; xv[4 * i + 3] = v.w;
    }

    float yl[HID], yr[HID];
#pragma unroll
    for (int o = 0; o < HID; o++) {
        float al = 0.0f, ar = 0.0f;
#pragma unroll
        for (int kk = 0; kk < IN_CH / 4; kk++) {
            float4 wl = *reinterpret_cast<float4*>(&swl[o * IN_CH + kk * 4]);
            float4 wr = *reinterpret_cast<float4*>(&swr[o * IN_CH + kk * 4]);
            al += xv[kk*4+0]*wl.x + xv[kk*4+1]*wl.y + xv[kk*4+2]*wl.z + xv[kk*4+3]*wl.w;
            ar += xv[kk*4+0]*wr.x + xv[kk*4+1]*wr.y + xv[kk*4+2]*wr.z + xv[kk*4+3]*wr.w;
        }
        yl[o] = al; yr[o] = ar;
    }

    float4* yp  = reinterpret_cast<float4*>(g_y  + (size_t)n * HID);
    float4* rp  = reinterpret_cast<float4*>(g_xr + (size_t)n * HID);
    float4* a1p = reinterpret_cast<float4*>(g_agg1 + (size_t)n * HID);
#pragma unroll
    for (int i = 0; i < HID / 4; i++) {
        yp[i] = make_float4(yl[4*i], yl[4*i+1], yl[4*i+2], yl[4*i+3]);
        rp[i] = make_float4(yr[4*i], yr[4*i+1], yr[4*i+2], yr[4*i+3]);
        a1p[i] = make_float4(0.f, 0.f, 0.f, 0.f);
    }
    g_cnt[n] = 0.0f;
}

// ---------------- Kernel B/D: edge scatter, 4 threads/edge (coalesced quad) ----------------
__global__ void __launch_bounds__(256) kScatter4(const int* __restrict__ ei,
                                                 const float* __restrict__ val,
                                                 float* __restrict__ acc,
                                                 int addCount) {
    int idx = blockIdx.x * blockDim.x + threadIdx.x;
    int e = idx >> 2;
    if (e >= N_EDGESC) return;
    int c = idx & 3;
    int s = __ldg(&ei[e]);                 // same addr across quad -> broadcast
    int d = __ldg(&ei[N_EDGESC + e]);

    // quad reads consecutive 16B chunks of the 64B source row -> 1 wavefront
    float4 v = __ldg(reinterpret_cast<const float4*>(val + (size_t)s * HID) + c);
    // quad REDs consecutive 16B chunks of the 64B dest row -> 1 wavefront
    red_add_v4(acc + (size_t)d * HID + c * 4, v.x, v.y, v.z, v.w);
    if (addCount && c == 0) atomicAdd(&g_cnt[d], 1.0f);
}

// ---------------- Kernel C: h1 = relu(agg1/cnt + b1 + xr); zero agg2 ----------------
__global__ void __launch_bounds__(256) kLayer1(const float* __restrict__ b1) {
    int idx = blockIdx.x * blockDim.x + threadIdx.x;
    if (idx >= N_NODESC * 4) return;
    int n = idx >> 2;
    int c = idx & 3;

    float inv = 1.0f / fmaxf(g_cnt[n], 1.0f);
    float4 a = *reinterpret_cast<float4*>(&g_agg1[(size_t)n * HID + c * 4]);
    float4 r = *reinterpret_cast<float4*>(&g_xr[(size_t)n * HID + c * 4]);
    float4 bb = __ldg(reinterpret_cast<const float4*>(b1) + c);

    float4 h;
    h.x = fmaxf(a.x * inv + bb.x + r.x, 0.0f);
    h.y = fmaxf(a.y * inv + bb.y + r.y, 0.0f);
    h.z = fmaxf(a.z * inv + bb.z + r.z, 0.0f);
    h.w = fmaxf(a.w * inv + bb.w + r.w, 0.0f);

    *reinterpret_cast<float4*>(&g_h1[(size_t)n * HID + c * 4]) = h;
    *reinterpret_cast<float4*>(&g_agg2[(size_t)n * HID + c * 4]) = make_float4(0.f, 0.f, 0.f, 0.f);
}

// ---------------- Kernel E: node GEMV + warp-aggregated graph readout ----------------
__global__ void __launch_bounds__(128) kLayer2(const int* __restrict__ batch,
                                               const float* __restrict__ w2l,
                                               const float* __restrict__ b2,
                                               const float* __restrict__ w2r) {
    __shared__ __align__(16) float swl[HID * OUT_CH];   // transposed [k][o]
    __shared__ __align__(16) float swr[HID * OUT_CH];
    __shared__ __align__(16) float sb2[OUT_CH];
    int t = threadIdx.x;
    for (int i = t; i < HID * OUT_CH; i += blockDim.x) {
        int o = i / HID, k = i % HID;
        swl[k * OUT_CH + o] = w2l[i];
        swr[k * OUT_CH + o] = w2r[i];
    }
    for (int i = t; i < OUT_CH; i += blockDim.x) sb2[i] = b2[i];
    __syncthreads();

    int n = blockIdx.x * blockDim.x + t;
    bool valid = n < N_NODESC;
    int nn = valid ? n : (N_NODESC - 1);
    int lane = t & 31;

    float inv = 1.0f / fmaxf(g_cnt[nn], 1.0f);
    float av[HID], hv[HID];
    const float4* ap = reinterpret_cast<const float4*>(g_agg2 + (size_t)nn * HID);
    const float4* hp = reinterpret_cast<const float4*>(g_h1 + (size_t)nn * HID);
#pragma unroll
    for (int i = 0; i < HID / 4; i++) {
        float4 a = ap[i];
        av[4*i] = a.x * inv; av[4*i+1] = a.y * inv; av[4*i+2] = a.z * inv; av[4*i+3] = a.w * inv;
        float4 h = hp[i];
        hv[4*i] = h.x; hv[4*i+1] = h.y; hv[4*i+2] = h.z; hv[4*i+3] = h.w;
    }

    float acc[OUT_CH];
#pragma unroll
    for (int o = 0; o < OUT_CH; o++) acc[o] = sb2[o];

#pragma unroll
    for (int k = 0; k < HID; k++) {
        float ak = av[k], hk = hv[k];
#pragma unroll
        for (int o = 0; o < OUT_CH; o += 4) {
            float4 wl = *reinterpret_cast<float4*>(&swl[k * OUT_CH + o]);
            float4 wr = *reinterpret_cast<float4*>(&swr[k * OUT_CH + o]);
            acc[o + 0] += ak * wl.x + hk * wr.x;
            acc[o + 1] += ak * wl.y + hk * wr.y;
            acc[o + 2] += ak * wl.z + hk * wr.z;
            acc[o + 3] += ak * wl.w + hk * wr.w;
        }
    }

    if (!valid) {
#pragma unroll
        for (int o = 0; o < OUT_CH; o++) acc[o] = 0.0f;
    }

    int g = __ldg(&batch[nn]);
    int g0 = __shfl_sync(0xffffffffu, g, 0);
    bool uni = __all_sync(0xffffffffu, g == g0);
    int nvalid = __popc(__ballot_sync(0xffffffffu, valid));

    if (uni) {
        // batch is sorted -> nearly every warp is graph-uniform
#pragma unroll
        for (int o = 0; o < OUT_CH; o++) {
            float v = acc[o];
            v += __shfl_xor_sync(0xffffffffu, v, 16);
            v += __shfl_xor_sync(0xffffffffu, v, 8);
            v += __shfl_xor_sync(0xffffffffu, v, 4);
            v += __shfl_xor_sync(0xffffffffu, v, 2);
            v += __shfl_xor_sync(0xffffffffu, v, 1);
            acc[o] = v;
        }
        if (lane == 0 && nvalid > 0) {
            float* gp = g_gacc + (size_t)g0 * OUT_CH;
#pragma unroll
            for (int o = 0; o < OUT_CH; o += 4)
                red_add_v4(gp + o, acc[o], acc[o + 1], acc[o + 2], acc[o + 3]);
            atomicAdd(&g_gcnt[g0], (float)nvalid);
        }
    } else if (valid) {
        float* gp = g_gacc + (size_t)g * OUT_CH;
#pragma unroll
        for (int o = 0; o < OUT_CH; o += 4)
            red_add_v4(gp + o, acc[o], acc[o + 1], acc[o + 2], acc[o + 3]);
        atomicAdd(&g_gcnt[g], 1.0f);
    }
}

// ---------------- Kernel F: final divide into d_out ----------------
__global__ void __launch_bounds__(256) kFinal(float* __restrict__ out) {
    int i = blockIdx.x * blockDim.x + threadIdx.x;
    if (i >= NUM_GRAPHS * OUT_CH) return;
    out[i] = g_gacc[i] / fmaxf(g_gcnt[i >> 6], 1.0f);
}

// ---------------- launch ----------------
extern "C" void kernel_launch(void* const* d_in, const int* in_sizes, int n_in,
                              void* d_out, int out_size) {
    const float* x    = (const float*)d_in[0];
    const int*   ei   = (const int*)d_in[1];
    const int*   batch= (const int*)d_in[2];
    const float* w1l  = (const float*)d_in[3];
    const float* b1   = (const float*)d_in[4];
    const float* w1r  = (const float*)d_in[5];
    const float* w2l  = (const float*)d_in[6];
    const float* b2   = (const float*)d_in[7];
    const float* w2r  = (const float*)d_in[8];
    float* out = (float*)d_out;

    float* gy;   cudaGetSymbolAddress((void**)&gy,   g_y);
    float* gh1;  cudaGetSymbolAddress((void**)&gh1,  g_h1);
    float* ga1;  cudaGetSymbolAddress((void**)&ga1,  g_agg1);
    float* ga2;  cudaGetSymbolAddress((void**)&ga2,  g_agg2);

    const int TB = 256;
    int nodeBlocks = (N_NODESC + TB - 1) / TB;
    int quadBlocks = ((N_EDGESC * 4) + TB - 1) / TB;
    int chBlocks   = (N_NODESC * 4 + TB - 1) / TB;

    kPre<<<nodeBlocks, TB>>>(x, w1l, w1r);
    kScatter4<<<quadBlocks, TB>>>(ei, gy, ga1, 1);
    kLayer1<<<chBlocks, TB>>>(b1);
    kScatter4<<<quadBlocks, TB>>>(ei, gh1, ga2, 0);
    kLayer2<<<(N_NODESC + 127) / 128, 128>>>(batch, w2l, b2, w2r);
    kFinal<<<(NUM_GRAPHS * OUT_CH + TB - 1) / TB, TB>>>(out);
}